// round 6
// baseline (speedup 1.0000x reference)
#include <cuda_runtime.h>

#define N    8192
#define DIM  128
#define E    262144
#define NB   32          // CSR-build blocks
#define EPB  (E / NB)    // 8192 edges per block
#define ASTR 132         // padded A row stride (floats)

// Scratch (device globals -- allocation-free per harness rules)
__device__ float g_inv_nrm[N];
__device__ float g_dis[N];            // rsqrt(deg+1)
__device__ int   g_cnt[N];            // in-degree (excl. self loop)
__device__ int   g_start[N];          // CSR start offsets
__device__ int   g_part[N * NB];      // partial histograms, TRANSPOSED [node][block]
__device__ int   g_prefix[N * NB];    // per-node exclusive prefix over blocks
__device__ int   g_csr[E];            // CSR: source node per slot
__device__ float g_M[DIM * DIM];      // Y^T x
__device__ float g_dxw[N * DIM];      // x @ W   (UNSCALED)
__device__ float g_gate[N * DIM];     // sigmoid(y . M)

// ----------------- chain B1: per-block histogram in smem, transposed spill
__global__ void k_hist(const int* __restrict__ ei) {
    __shared__ int sc[N];
    int tid = threadIdx.x;
    for (int i = tid; i < N / 4; i += 256) ((int4*)sc)[i] = make_int4(0, 0, 0, 0);
    __syncthreads();
    const int4* c4 = (const int4*)(ei + E) + blockIdx.x * (EPB / 4);
    for (int i = tid; i < EPB / 4; i += 256) {
        int4 c = c4[i];
        atomicAdd(&sc[c.x], 1); atomicAdd(&sc[c.y], 1);
        atomicAdd(&sc[c.z], 1); atomicAdd(&sc[c.w], 1);
    }
    __syncthreads();
    int b = blockIdx.x;
    for (int i = tid; i < N; i += 256) g_part[i * NB + b] = sc[i];
}

// ----------------- chain B2: warp-per-node reduce + prefix + dis (one pass)
__global__ void k_reduce() {
    int w = threadIdx.x >> 5, lane = threadIdx.x & 31;
    int node = blockIdx.x * 8 + w;
    int v = g_part[node * NB + lane];          // coalesced 128B per warp
    int c = v;
    #pragma unroll
    for (int o = 1; o < 32; o <<= 1) {         // inclusive scan
        int t = __shfl_up_sync(0xffffffffu, v, o);
        if (lane >= o) v += t;
    }
    g_prefix[node * NB + lane] = v - c;        // exclusive prefix, coalesced
    int total = __shfl_sync(0xffffffffu, v, 31);
    if (lane == 0) {
        g_cnt[node] = total;
        g_dis[node] = rsqrtf((float)(total + 1));
    }
}

// ----------------- chain B3: exclusive scan over 8192 counts (1 block)
__global__ void k_scan() {
    __shared__ int warp_sums[32];
    int tid = threadIdx.x;            // 1024 threads, 8 counters each
    int base = tid * 8;
    int c[8], s = 0;
    #pragma unroll
    for (int j = 0; j < 8; j++) { c[j] = g_cnt[base + j]; s += c[j]; }
    int lane = tid & 31, w = tid >> 5;
    int v = s;
    #pragma unroll
    for (int o = 1; o < 32; o <<= 1) {
        int t = __shfl_up_sync(0xffffffffu, v, o);
        if (lane >= o) v += t;
    }
    if (lane == 31) warp_sums[w] = v;
    __syncthreads();
    if (w == 0) {
        int ws = warp_sums[lane];
        #pragma unroll
        for (int o = 1; o < 32; o <<= 1) {
            int t = __shfl_up_sync(0xffffffffu, ws, o);
            if (lane >= o) ws += t;
        }
        warp_sums[lane] = ws;
    }
    __syncthreads();
    int run = v - s + (w > 0 ? warp_sums[w - 1] : 0);
    #pragma unroll
    for (int j = 0; j < 8; j++) { g_start[base + j] = run; run += c[j]; }
}

// ----------------- chain B4: CSR fill, SMEM cursors from start+prefix
__global__ void k_fill(const int* __restrict__ ei) {
    __shared__ int cur[N];
    int tid = threadIdx.x;
    int b = blockIdx.x;
    for (int i = tid; i < N; i += 256)
        cur[i] = g_start[i] + g_prefix[i * NB + b];
    __syncthreads();
    const int4* r4 = (const int4*)ei + b * (EPB / 4);
    const int4* c4 = (const int4*)(ei + E) + b * (EPB / 4);
    for (int i = tid; i < EPB / 4; i += 256) {
        int4 r = r4[i];
        int4 c = c4[i];
        g_csr[atomicAdd(&cur[c.x], 1)] = r.x;
        g_csr[atomicAdd(&cur[c.y], 1)] = r.y;
        g_csr[atomicAdd(&cur[c.z], 1)] = r.z;
        g_csr[atomicAdd(&cur[c.w], 1)] = r.w;
    }
}

// ----------------- main A1: row inverse norms + zero M
__global__ void k_norms(const float* __restrict__ x) {
    int tid = threadIdx.x;
    int gi = blockIdx.x * 256 + tid;
    if (gi < DIM * DIM) g_M[gi] = 0.f;
    int w = tid >> 5, lane = tid & 31;
    int row = blockIdx.x * 8 + w;
    float4 v = ((const float4*)x)[row * 32 + lane];
    float s = v.x * v.x + v.y * v.y + v.z * v.z + v.w * v.w;
    #pragma unroll
    for (int o = 16; o; o >>= 1) s += __shfl_xor_sync(0xffffffffu, s, o);
    if (lane == 0) g_inv_nrm[row] = rsqrtf(s);
}

// ----------------- main A2: M = Y^T x (128x128), 8x8 tiles + atomics
__global__ void k_maccum(const float* __restrict__ x) {
    __shared__ float xs[8][DIM];
    __shared__ float invs[8];
    int tid = threadIdx.x;
    int tx = tid & 15, ty = tid >> 4;
    int k0 = ty * 8, d0 = tx * 8;
    float acc[8][8] = {};
    int row_base = blockIdx.x * 64;
    for (int p = 0; p < 8; p++) {
        int r0 = row_base + p * 8;
        {
            int rr = tid >> 5, cc = tid & 31;
            float4 v = ((const float4*)x)[(r0 + rr) * 32 + cc];
            ((float4*)&xs[rr][0])[cc] = v;
        }
        if (tid < 8) invs[tid] = g_inv_nrm[r0 + tid];
        __syncthreads();
        #pragma unroll
        for (int r = 0; r < 8; r++) {
            float inv = invs[r];
            float yk[8], xd[8];
            #pragma unroll
            for (int j = 0; j < 8; j++) yk[j] = xs[r][k0 + j] * inv;
            #pragma unroll
            for (int l = 0; l < 8; l++) xd[l] = xs[r][d0 + l];
            #pragma unroll
            for (int j = 0; j < 8; j++)
                #pragma unroll
                for (int l = 0; l < 8; l++)
                    acc[j][l] += yk[j] * xd[l];
        }
        __syncthreads();
    }
    #pragma unroll
    for (int j = 0; j < 8; j++)
        #pragma unroll
        for (int l = 0; l < 8; l++)
            atomicAdd(&g_M[(k0 + j) * DIM + (d0 + l)], acc[j][l]);
}

// ----------------- GEMM P = x @ B, 128x128 tile, 8x8/thread
// mode 0: B=W   -> g_dxw  (unscaled)
// mode 1: B=g_M -> g_gate = sigmoid(P * inv_nrm[row])
__global__ void k_gemm(const float* __restrict__ x, const float* __restrict__ Bp,
                       int mode) {
    extern __shared__ float sm[];
    float* As = sm;                    // [128][ASTR]
    float* Bs = sm + 128 * ASTR;       // [128][128]
    int tid = threadIdx.x;
    int tx = tid & 15, ty = tid >> 4;
    int rb = blockIdx.x * 128;
    const float* B = (mode == 0) ? Bp : g_M;

    #pragma unroll
    for (int i = 0; i < 16; i++) {
        int f = i * 256 + tid;
        int row = f >> 5, c4 = f & 31;
        float4 v = ((const float4*)x)[(rb + row) * 32 + c4];
        *((float4*)&As[row * ASTR + c4 * 4]) = v;
        ((float4*)Bs)[f] = ((const float4*)B)[f];
    }
    __syncthreads();

    int r0 = ty * 8;
    float acc[8][8] = {};
    #pragma unroll 8
    for (int k = 0; k < DIM; k++) {
        float a[8];
        #pragma unroll
        for (int i = 0; i < 8; i++) a[i] = As[(r0 + i) * ASTR + k];
        float4 b0 = ((float4*)Bs)[k * 32 + tx * 2];
        float4 b1 = ((float4*)Bs)[k * 32 + tx * 2 + 1];
        float b[8] = {b0.x, b0.y, b0.z, b0.w, b1.x, b1.y, b1.z, b1.w};
        #pragma unroll
        for (int i = 0; i < 8; i++)
            #pragma unroll
            for (int j = 0; j < 8; j++)
                acc[i][j] += a[i] * b[j];
    }

    if (mode == 0) {
        #pragma unroll
        for (int i = 0; i < 8; i++) {
            int grow = rb + r0 + i;
            ((float4*)g_dxw)[grow * 32 + tx * 2] =
                make_float4(acc[i][0], acc[i][1], acc[i][2], acc[i][3]);
            ((float4*)g_dxw)[grow * 32 + tx * 2 + 1] =
                make_float4(acc[i][4], acc[i][5], acc[i][6], acc[i][7]);
        }
    } else {
        #pragma unroll
        for (int i = 0; i < 8; i++) {
            int grow = rb + r0 + i;
            float s = g_inv_nrm[grow];
            float o[8];
            #pragma unroll
            for (int j = 0; j < 8; j++)
                o[j] = 1.f / (1.f + __expf(-acc[i][j] * s));
            ((float4*)g_gate)[grow * 32 + tx * 2]     = make_float4(o[0], o[1], o[2], o[3]);
            ((float4*)g_gate)[grow * 32 + tx * 2 + 1] = make_float4(o[4], o[5], o[6], o[7]);
        }
    }
}

// ----------------- join: CSR gather (dis[src] applied here) + gate + bias
__global__ void k_final(const float* __restrict__ b, float* __restrict__ out) {
    int tid = threadIdx.x;
    int w = tid >> 5, lane = tid & 31;
    int node = blockIdx.x * 8 + w;
    const float4* dxw4 = (const float4*)g_dxw;

    int s0  = g_start[node];
    int cnt = g_cnt[node];
    float dn = g_dis[node];
    float4 self = dxw4[node * 32 + lane];
    float4 acc;
    acc.x = self.x * dn; acc.y = self.y * dn;
    acc.z = self.z * dn; acc.w = self.w * dn;
    int j = 0;
    for (; j + 4 <= cnt; j += 4) {
        int i0 = __ldg(&g_csr[s0 + j]);
        int i1 = __ldg(&g_csr[s0 + j + 1]);
        int i2 = __ldg(&g_csr[s0 + j + 2]);
        int i3 = __ldg(&g_csr[s0 + j + 3]);
        float d0 = __ldg(&g_dis[i0]), d1 = __ldg(&g_dis[i1]);
        float d2 = __ldg(&g_dis[i2]), d3 = __ldg(&g_dis[i3]);
        float4 v0 = dxw4[i0 * 32 + lane];
        float4 v1 = dxw4[i1 * 32 + lane];
        float4 v2 = dxw4[i2 * 32 + lane];
        float4 v3 = dxw4[i3 * 32 + lane];
        acc.x += v0.x * d0 + v1.x * d1 + v2.x * d2 + v3.x * d3;
        acc.y += v0.y * d0 + v1.y * d1 + v2.y * d2 + v3.y * d3;
        acc.z += v0.z * d0 + v1.z * d1 + v2.z * d2 + v3.z * d3;
        acc.w += v0.w * d0 + v1.w * d1 + v2.w * d2 + v3.w * d3;
    }
    for (; j < cnt; j++) {
        int i0 = __ldg(&g_csr[s0 + j]);
        float d0 = __ldg(&g_dis[i0]);
        float4 v0 = dxw4[i0 * 32 + lane];
        acc.x += v0.x * d0; acc.y += v0.y * d0;
        acc.z += v0.z * d0; acc.w += v0.w * d0;
    }
    float4 bb = ((const float4*)b)[lane];
    float4 a  = ((const float4*)g_gate)[node * 32 + lane];
    float4 o;
    o.x = (acc.x * dn + bb.x) * a.x;
    o.y = (acc.y * dn + bb.y) * a.y;
    o.z = (acc.z * dn + bb.z) * a.z;
    o.w = (acc.w * dn + bb.w) * a.w;
    ((float4*)out)[node * 32 + lane] = o;
}

// ---------------------------------------------------------------- launcher
extern "C" void kernel_launch(void* const* d_in, const int* in_sizes, int n_in,
                              void* d_out, int out_size) {
    const float* x  = (const float*)d_in[0];
    const int*   ei = (const int*)d_in[1];
    const float* W  = (const float*)d_in[2];
    const float* b  = (const float*)d_in[3];
    float* out = (float*)d_out;

    static bool init_done = false;
    static cudaStream_t sB, sC;
    static cudaEvent_t evRoot, evB, evC;
    if (!init_done) {
        cudaStreamCreateWithFlags(&sB, cudaStreamNonBlocking);
        cudaStreamCreateWithFlags(&sC, cudaStreamNonBlocking);
        cudaEventCreateWithFlags(&evRoot, cudaEventDisableTiming);
        cudaEventCreateWithFlags(&evB,    cudaEventDisableTiming);
        cudaEventCreateWithFlags(&evC,    cudaEventDisableTiming);
        const int SMEM_G = (128 * ASTR + 128 * 128) * 4;
        cudaFuncSetAttribute(k_gemm, cudaFuncAttributeMaxDynamicSharedMemorySize, SMEM_G);
        init_done = true;
    }
    const int SMEM_G = (128 * ASTR + 128 * 128) * 4;

    // fork
    cudaEventRecord(evRoot, 0);
    cudaStreamWaitEvent(sB, evRoot, 0);
    cudaStreamWaitEvent(sC, evRoot, 0);

    // chain B: CSR build (latency-bound; overlaps compute chains)
    k_hist  <<<NB, 256, 0, sB>>>(ei);
    k_reduce<<<N / 8, 256, 0, sB>>>();
    k_scan  <<<1, 1024, 0, sB>>>();
    k_fill  <<<NB, 256, 0, sB>>>(ei);
    cudaEventRecord(evB, sB);

    // chain C: x @ W (no dependencies)
    k_gemm<<<64, 256, SMEM_G, sC>>>(x, W, 0);
    cudaEventRecord(evC, sC);

    // main chain: norms -> M -> gate
    k_norms <<<N / 8, 256>>>(x);
    k_maccum<<<128, 256>>>(x);
    k_gemm  <<<64, 256, SMEM_G>>>(x, nullptr, 1);

    // join
    cudaStreamWaitEvent(0, evB, 0);
    cudaStreamWaitEvent(0, evC, 0);
    k_final<<<N / 8, 256>>>(b, out);
}

// round 7
// speedup vs baseline: 1.1797x; 1.1797x over previous
#include <cuda_runtime.h>

#define N    8192
#define DIM  128
#define E    262144
#define ASTR 132   // padded A row stride (floats)

// Scratch (device globals -- allocation-free per harness rules)
__device__ float g_inv_nrm[N];
__device__ float g_dis[N];            // rsqrt(deg+1)
__device__ int   g_cnt[N];            // in-degree (excl. self loop)
__device__ int   g_start[N];          // CSR start offsets
__device__ int   g_cursor[N];         // fill cursors
__device__ int   g_csr[E];            // CSR: source node per slot
__device__ float g_M[DIM * DIM];      // Y^T x
__device__ float g_dxw[N * DIM];      // x @ W   (UNSCALED)
__device__ float g_gate[N * DIM];     // sigmoid(y . M)

// ----------------- chain B1: in-degree histogram, wide grid
__global__ void k_hist(const int* __restrict__ ei) {
    int i = blockIdx.x * blockDim.x + threadIdx.x;
    atomicAdd(&g_cnt[__ldg(&ei[E + i])], 1);
}

// ----------------- chain B2: scan 8192 counts -> start/cursor/dis (1 block)
__global__ void k_scan() {
    __shared__ int warp_sums[32];
    int tid = threadIdx.x;            // 1024 threads, 8 counters each
    int base = tid * 8;
    int c[8], s = 0;
    #pragma unroll
    for (int j = 0; j < 8; j++) { c[j] = g_cnt[base + j]; s += c[j]; }
    int lane = tid & 31, w = tid >> 5;
    int v = s;
    #pragma unroll
    for (int o = 1; o < 32; o <<= 1) {
        int t = __shfl_up_sync(0xffffffffu, v, o);
        if (lane >= o) v += t;
    }
    if (lane == 31) warp_sums[w] = v;
    __syncthreads();
    if (w == 0) {
        int ws = warp_sums[lane];
        #pragma unroll
        for (int o = 1; o < 32; o <<= 1) {
            int t = __shfl_up_sync(0xffffffffu, ws, o);
            if (lane >= o) ws += t;
        }
        warp_sums[lane] = ws;
    }
    __syncthreads();
    int run = v - s + (w > 0 ? warp_sums[w - 1] : 0);
    #pragma unroll
    for (int j = 0; j < 8; j++) {
        g_start[base + j]  = run;
        g_cursor[base + j] = run;
        g_dis[base + j]    = rsqrtf((float)(c[j] + 1));
        run += c[j];
    }
}

// ----------------- chain B3: CSR fill, wide grid, global atomic cursors
__global__ void k_fill(const int* __restrict__ ei) {
    int i = blockIdx.x * blockDim.x + threadIdx.x;
    int r = __ldg(&ei[i]);
    int c = __ldg(&ei[E + i]);
    g_csr[atomicAdd(&g_cursor[c], 1)] = r;
}

// ----------------- main A0: zero M + zero cnt
__global__ void k_zero() {
    int i = blockIdx.x * 1024 + threadIdx.x;
    if (i < DIM * DIM) g_M[i] = 0.f;
    // (g_cnt zeroed in chain B head below via same kernel on sB)
}
__global__ void k_zcnt() {
    int i = blockIdx.x * 1024 + threadIdx.x;
    g_cnt[i] = 0;
}

// ----------------- main A1: M = Y^T x (128x128) with FUSED row norms
__global__ void k_maccum(const float* __restrict__ x) {
    __shared__ float xs[8][DIM];
    __shared__ float invs[8];
    int tid = threadIdx.x;
    int tx = tid & 15, ty = tid >> 4;
    int k0 = ty * 8, d0 = tx * 8;
    float acc[8][8] = {};
    int row_base = blockIdx.x * 64;
    for (int p = 0; p < 8; p++) {
        int r0 = row_base + p * 8;
        {   // warp rr stages row r0+rr and computes its inverse norm
            int rr = tid >> 5, cc = tid & 31;
            float4 v = ((const float4*)x)[(r0 + rr) * 32 + cc];
            ((float4*)&xs[rr][0])[cc] = v;
            float s = v.x * v.x + v.y * v.y + v.z * v.z + v.w * v.w;
            #pragma unroll
            for (int o = 16; o; o >>= 1) s += __shfl_xor_sync(0xffffffffu, s, o);
            if (cc == 0) {
                float inv = rsqrtf(s);
                invs[rr] = inv;
                g_inv_nrm[r0 + rr] = inv;
            }
        }
        __syncthreads();
        #pragma unroll
        for (int r = 0; r < 8; r++) {
            float inv = invs[r];
            float yk[8], xd[8];
            #pragma unroll
            for (int j = 0; j < 8; j++) yk[j] = xs[r][k0 + j] * inv;
            #pragma unroll
            for (int l = 0; l < 8; l++) xd[l] = xs[r][d0 + l];
            #pragma unroll
            for (int j = 0; j < 8; j++)
                #pragma unroll
                for (int l = 0; l < 8; l++)
                    acc[j][l] += yk[j] * xd[l];
        }
        __syncthreads();
    }
    #pragma unroll
    for (int j = 0; j < 8; j++)
        #pragma unroll
        for (int l = 0; l < 8; l++)
            atomicAdd(&g_M[(k0 + j) * DIM + (d0 + l)], acc[j][l]);
}

// ----------------- GEMM P = x @ B, 64x128 tile, grid 128, 8x4/thread
// mode 0: B=W   -> g_dxw  (unscaled)
// mode 1: B=g_M -> g_gate = sigmoid(P * inv_nrm[row])
__global__ void k_gemm(const float* __restrict__ x, const float* __restrict__ Bp,
                       int mode) {
    extern __shared__ float sm[];
    float* As = sm;                    // [64][ASTR]
    float* Bs = sm + 64 * ASTR;        // [128][128]
    int tid = threadIdx.x;
    int tx = tid & 31, ty = tid >> 5;  // tx: float4 col, ty: 8-row group
    int rb = blockIdx.x * 64;
    const float* B = (mode == 0) ? Bp : g_M;

    #pragma unroll
    for (int i = 0; i < 8; i++) {      // A: 64 rows x 32 float4
        int f = i * 256 + tid;
        int row = f >> 5, c4 = f & 31;
        float4 v = ((const float4*)x)[(rb + row) * 32 + c4];
        *((float4*)&As[row * ASTR + c4 * 4]) = v;
    }
    #pragma unroll
    for (int i = 0; i < 16; i++) {     // B: 4096 float4
        int f = i * 256 + tid;
        ((float4*)Bs)[f] = ((const float4*)B)[f];
    }
    __syncthreads();

    int r0 = ty * 8;
    float4 acc[8];
    #pragma unroll
    for (int i = 0; i < 8; i++) acc[i] = make_float4(0.f, 0.f, 0.f, 0.f);
    #pragma unroll 8
    for (int k = 0; k < DIM; k++) {
        float4 bv = ((float4*)Bs)[k * 32 + tx];
        #pragma unroll
        for (int i = 0; i < 8; i++) {
            float a = As[(r0 + i) * ASTR + k];   // warp-broadcast
            acc[i].x += a * bv.x; acc[i].y += a * bv.y;
            acc[i].z += a * bv.z; acc[i].w += a * bv.w;
        }
    }

    if (mode == 0) {
        #pragma unroll
        for (int i = 0; i < 8; i++)
            ((float4*)g_dxw)[(rb + r0 + i) * 32 + tx] = acc[i];
    } else {
        #pragma unroll
        for (int i = 0; i < 8; i++) {
            int grow = rb + r0 + i;
            float s = g_inv_nrm[grow];
            float4 o;
            o.x = 1.f / (1.f + __expf(-acc[i].x * s));
            o.y = 1.f / (1.f + __expf(-acc[i].y * s));
            o.z = 1.f / (1.f + __expf(-acc[i].z * s));
            o.w = 1.f / (1.f + __expf(-acc[i].w * s));
            ((float4*)g_gate)[grow * 32 + tx] = o;
        }
    }
}

// ----------------- join: CSR gather (dis[src] applied here) + gate + bias
__global__ void k_final(const float* __restrict__ b, float* __restrict__ out) {
    int tid = threadIdx.x;
    int w = tid >> 5, lane = tid & 31;
    int node = blockIdx.x * 8 + w;
    const float4* dxw4 = (const float4*)g_dxw;

    int s0  = g_start[node];
    int cnt = g_cnt[node];
    float dn = g_dis[node];
    float4 self = dxw4[node * 32 + lane];
    float4 acc;
    acc.x = self.x * dn; acc.y = self.y * dn;
    acc.z = self.z * dn; acc.w = self.w * dn;
    int j = 0;
    for (; j + 4 <= cnt; j += 4) {
        int i0 = __ldg(&g_csr[s0 + j]);
        int i1 = __ldg(&g_csr[s0 + j + 1]);
        int i2 = __ldg(&g_csr[s0 + j + 2]);
        int i3 = __ldg(&g_csr[s0 + j + 3]);
        float d0 = __ldg(&g_dis[i0]), d1 = __ldg(&g_dis[i1]);
        float d2 = __ldg(&g_dis[i2]), d3 = __ldg(&g_dis[i3]);
        float4 v0 = dxw4[i0 * 32 + lane];
        float4 v1 = dxw4[i1 * 32 + lane];
        float4 v2 = dxw4[i2 * 32 + lane];
        float4 v3 = dxw4[i3 * 32 + lane];
        acc.x += v0.x * d0 + v1.x * d1 + v2.x * d2 + v3.x * d3;
        acc.y += v0.y * d0 + v1.y * d1 + v2.y * d2 + v3.y * d3;
        acc.z += v0.z * d0 + v1.z * d1 + v2.z * d2 + v3.z * d3;
        acc.w += v0.w * d0 + v1.w * d1 + v2.w * d2 + v3.w * d3;
    }
    for (; j < cnt; j++) {
        int i0 = __ldg(&g_csr[s0 + j]);
        float d0 = __ldg(&g_dis[i0]);
        float4 v0 = dxw4[i0 * 32 + lane];
        acc.x += v0.x * d0; acc.y += v0.y * d0;
        acc.z += v0.z * d0; acc.w += v0.w * d0;
    }
    float4 bb = ((const float4*)b)[lane];
    float4 a  = ((const float4*)g_gate)[node * 32 + lane];
    float4 o;
    o.x = (acc.x * dn + bb.x) * a.x;
    o.y = (acc.y * dn + bb.y) * a.y;
    o.z = (acc.z * dn + bb.z) * a.z;
    o.w = (acc.w * dn + bb.w) * a.w;
    ((float4*)out)[node * 32 + lane] = o;
}

// ---------------------------------------------------------------- launcher
extern "C" void kernel_launch(void* const* d_in, const int* in_sizes, int n_in,
                              void* d_out, int out_size) {
    const float* x  = (const float*)d_in[0];
    const int*   ei = (const int*)d_in[1];
    const float* W  = (const float*)d_in[2];
    const float* b  = (const float*)d_in[3];
    float* out = (float*)d_out;

    const int SMEM_G = (64 * ASTR + 128 * 128) * 4;   // ~97 KB
    static bool init_done = false;
    static cudaStream_t sB, sC;
    static cudaEvent_t evRoot, evB, evC;
    if (!init_done) {
        cudaStreamCreateWithFlags(&sB, cudaStreamNonBlocking);
        cudaStreamCreateWithFlags(&sC, cudaStreamNonBlocking);
        cudaEventCreateWithFlags(&evRoot, cudaEventDisableTiming);
        cudaEventCreateWithFlags(&evB,    cudaEventDisableTiming);
        cudaEventCreateWithFlags(&evC,    cudaEventDisableTiming);
        cudaFuncSetAttribute(k_gemm, cudaFuncAttributeMaxDynamicSharedMemorySize, SMEM_G);
        init_done = true;
    }

    // fork
    cudaEventRecord(evRoot, 0);
    cudaStreamWaitEvent(sB, evRoot, 0);
    cudaStreamWaitEvent(sC, evRoot, 0);

    // chain B: CSR build (latency-bound, wide grids; overlaps compute)
    k_zcnt<<<8, 1024, 0, sB>>>();
    k_hist<<<E / 256, 256, 0, sB>>>(ei);
    k_scan<<<1, 1024, 0, sB>>>();
    k_fill<<<E / 256, 256, 0, sB>>>(ei);
    cudaEventRecord(evB, sB);

    // chain C: x @ W (no dependencies)
    k_gemm<<<128, 256, SMEM_G, sC>>>(x, W, 0);
    cudaEventRecord(evC, sC);

    // main chain: zero M -> maccum(+norms) -> gate gemm
    k_zero  <<<16, 1024>>>();
    k_maccum<<<128, 256>>>(x);
    k_gemm  <<<128, 256, SMEM_G>>>(x, nullptr, 1);

    // join
    cudaStreamWaitEvent(0, evB, 0);
    cudaStreamWaitEvent(0, evC, 0);
    k_final<<<N / 8, 256>>>(b, out);
}